// round 6
// baseline (speedup 1.0000x reference)
#include <cuda_runtime.h>
#include <cuda_fp16.h>
#include <cstdint>

// NeuralSpectralBlock1d: fp16 2-pass mma.sync GEMM + warp-specialized overlap.
// Round 6: 16 GEMM warps || 4 epilogue warps (640 threads). Named-barrier handoff.
// CTA = 64 columns (16 patches) of one batch. Grid 2048.

#define THREADS 640

// SMEM byte offsets
#define XTHI 0u          // x^T fp16 [64 n][256 k], 16B-swizzled      (32768)
#define ABUF 32768u      // weight staging ping/pong 2x32768          (65536)
#define STG  98304u      // GEMM out f32 [256][65]                    (66560)
#define LT   164864u     // lt fp16 [256][66]                         (33792)
#define WS   198656u     // spectral weights f32 [256][24]            (24576)
#define LAT  223232u     // latent f32 [1024]                         (4096)
#define EB   227328u     // enc bias f32 [512]                        (2048)
#define DB   229376u     // dec bias f32 [256]                        (1024)
#define SMEM_REQ 230400u

// Pre-split weights: [kchunk 0..7][row 0..767][8 x 16B]; rows 0-511 enc, 512-767 dec.
// 16B cols: logical 0-3 = w_hi(k 0..31 of chunk), 4-7 = w_lo; stored col = logical ^ (row&7).
__device__ uint4 g_wsplit[8][768][8];

__global__ void prep_kernel(const float* __restrict__ enc_w, const float* __restrict__ dec_w) {
    int idx = blockIdx.x * blockDim.x + threadIdx.x;
    if (idx >= 768 * 32) return;
    int row = idx >> 5, c8 = idx & 31;
    const float* src = (row < 512) ? (enc_w + row * 256 + c8 * 8)
                                   : (dec_w + (row - 512) * 256 + c8 * 8);
    union { __half h[8]; uint4 u; } hi, lo;
#pragma unroll
    for (int i = 0; i < 8; i++) {
        float v = src[i];
        hi.h[i] = __float2half(v);
        lo.h[i] = __float2half(v - __half2float(hi.h[i]));
    }
    int chunk = c8 >> 2, lc = c8 & 3;
    g_wsplit[chunk][row][lc ^ (row & 7)]       = hi.u;
    g_wsplit[chunk][row][(lc + 4) ^ (row & 7)] = lo.u;
}

static __device__ __forceinline__ uint32_t smem_u32(const void* p) {
    uint32_t a;
    asm("{ .reg .u64 t; cvta.to.shared.u64 t, %1; cvt.u32.u64 %0, t; }" : "=r"(a) : "l"(p));
    return a;
}
static __device__ __forceinline__ void ldm4(uint32_t* d, uint32_t a) {
    asm volatile("ldmatrix.sync.aligned.m8n8.x4.shared.b16 {%0,%1,%2,%3}, [%4];"
                 : "=r"(d[0]), "=r"(d[1]), "=r"(d[2]), "=r"(d[3]) : "r"(a));
}
static __device__ __forceinline__ void mma16816(float* c, const uint32_t* a, const uint32_t* b) {
    asm volatile("mma.sync.aligned.m16n8k16.row.col.f32.f16.f16.f32 "
                 "{%0,%1,%2,%3}, {%4,%5,%6,%7}, {%8,%9}, {%0,%1,%2,%3};"
                 : "+f"(c[0]), "+f"(c[1]), "+f"(c[2]), "+f"(c[3])
                 : "r"(a[0]), "r"(a[1]), "r"(a[2]), "r"(a[3]), "r"(b[0]), "r"(b[1]));
}
static __device__ __forceinline__ void bar_sync(int id, int cnt) {
    asm volatile("bar.sync %0, %1;" :: "r"(id), "r"(cnt) : "memory");
}
static __device__ __forceinline__ void bar_arrive(int id, int cnt) {
    asm volatile("bar.arrive %0, %1;" :: "r"(id), "r"(cnt) : "memory");
}

// stage one 32KB weight chunk (rows r*256..+255) into ABUF buffer `buf` (GEMM threads, tid<512)
static __device__ __forceinline__ void stage_chunk(uint32_t sb, int r, int chunk, int buf, int tid) {
    int row = tid >> 1, half = tid & 1;
    const uint4* gsrc = &g_wsplit[chunk][r * 256 + row][half * 4];
    uint32_t dstb = sb + ABUF + (uint32_t)buf * 32768u + (uint32_t)row * 128u + (uint32_t)half * 64u;
#pragma unroll
    for (int i = 0; i < 4; i++)
        asm volatile("cp.async.cg.shared.global [%0], [%1], 16;"
                     :: "r"(dstb + i * 16), "l"(gsrc + i) : "memory");
    asm volatile("cp.async.commit_group;" ::: "memory");
}

__global__ __launch_bounds__(THREADS, 1)
void NeuralSpectralBlock1d_4509715661385_kernel(
    const float* __restrict__ x, const float* __restrict__ weights,
    const float* __restrict__ latent, const float* __restrict__ enc_b,
    const float* __restrict__ dec_b, float* __restrict__ out)
{
    extern __shared__ char smem[];
    const uint32_t sb = smem_u32(smem);

    float*  stg   = (float*)(smem + STG);   // [256][65]
    __half* lt_h  = (__half*)(smem + LT);   // [256][66]
    float*  w_s   = (float*)(smem + WS);    // [256][24]
    float*  lat_s = (float*)(smem + LAT);
    float*  eb_s  = (float*)(smem + EB);
    float*  db_s  = (float*)(smem + DB);

    const int tid = threadIdx.x;
    const int bx = blockIdx.x;
    const int batch = bx >> 6;
    const int hp0 = (bx & 63) * 16;
    const int h0 = hp0 * 4;
    const float* xg = x + (size_t)batch * 256 * 4096 + h0;
    float* og = out + (size_t)batch * 256 * 4096;

    if (tid < 512) stage_chunk(sb, 0, 0, 0, tid);   // prefetch round-0 chunk-0

    // ---- loads (all 640 threads): x tile fp16 swizzled, weights, latent, biases ----
    for (int idx = tid; idx < 64 * 256; idx += THREADS) {
        int j = idx & 63, c = idx >> 6;
        float v = xg[(size_t)c * 4096 + j];
        uint32_t off = (uint32_t)j * 512u + ((uint32_t)((c >> 3) ^ (j & 7)) << 4) + (uint32_t)(c & 7) * 2u;
        *(__half*)(smem + XTHI + off) = __float2half(v);
    }
    for (int idx = tid; idx < 256 * 24; idx += THREADS) w_s[idx] = weights[idx];
    for (int idx = tid; idx < 1024; idx += THREADS) lat_s[idx] = latent[idx];
    for (int idx = tid; idx < 512; idx += THREADS) eb_s[idx] = enc_b[idx];
    for (int idx = tid; idx < 256; idx += THREADS) db_s[idx] = dec_b[idx];
    __syncthreads();

    const unsigned FULL = 0xFFFFFFFFu;
    const float PI_OVER_NB = 0.26179938779914943653855361527329f;  // pi/12

    if (tid < 512) {
        // ======================= GEMM warps =======================
        const int wid = tid >> 5, lid = tid & 31;
        const int wm = wid & 7, wn = wid >> 3;
        const int a_row8 = (lid & 7) + ((lid >> 3) & 1) * 8;
        const int a_half = lid >> 4;
        const int b_n8   = (lid & 7) + ((lid >> 4) & 1) * 8;
        const int b_k8   = (lid >> 3) & 1;

#pragma unroll 1
        for (int r = 0; r < 3; r++) {
            float acc[2][4][4];
#pragma unroll
            for (int mt = 0; mt < 2; mt++)
#pragma unroll
                for (int nt = 0; nt < 4; nt++)
#pragma unroll
                    for (int q = 0; q < 4; q++) acc[mt][nt][q] = 0.f;

#pragma unroll 1
            for (int c = 0; c < 8; c++) {
                if (c < 7) {
                    stage_chunk(sb, r, c + 1, (c + 1) & 1, tid);
                    asm volatile("cp.async.wait_group 1;" ::: "memory");
                } else {
                    asm volatile("cp.async.wait_group 0;" ::: "memory");
                }
                bar_sync(1, 512);

                const uint32_t ab = sb + ABUF + (uint32_t)(c & 1) * 32768u;
#pragma unroll
                for (int s = 0; s < 2; s++) {
                    uint32_t ah[2][4], al[2][4];
#pragma unroll
                    for (int mt = 0; mt < 2; mt++) {
                        int row = wm * 32 + mt * 16 + a_row8;
                        int lch = 2 * s + a_half;
                        ldm4(ah[mt], ab + (uint32_t)row * 128u + ((uint32_t)(lch ^ (row & 7)) << 4));
                        int lcl = 4 + 2 * s + a_half;
                        ldm4(al[mt], ab + (uint32_t)row * 128u + ((uint32_t)(lcl ^ (row & 7)) << 4));
                    }
                    uint32_t bh[2][4];
#pragma unroll
                    for (int nb = 0; nb < 2; nb++) {
                        int n = (2 * wn + nb) * 16 + b_n8;
                        int col = c * 4 + 2 * s + b_k8;
                        uint32_t off = (uint32_t)n * 512u + ((uint32_t)(col ^ (n & 7)) << 4);
                        ldm4(bh[nb], sb + XTHI + off);
                    }
#pragma unroll
                    for (int mt = 0; mt < 2; mt++)
#pragma unroll
                        for (int nt = 0; nt < 4; nt++) {
                            const uint32_t* B0 = &bh[nt >> 1][(nt & 1) * 2];
                            mma16816(acc[mt][nt], ah[mt], B0);   // w_hi * x
                            mma16816(acc[mt][nt], al[mt], B0);   // w_lo * x
                        }
                }
                bar_sync(1, 512);
            }

            if (r >= 1) bar_sync(5, THREADS);   // wait: epilogue done reading stg (round r-1)

            // ---- dump acc -> stg (+bias) ----
            {
                const float* bias = (r < 2) ? (eb_s + r * 256) : db_s;
#pragma unroll
                for (int mt = 0; mt < 2; mt++) {
                    int r0 = wm * 32 + mt * 16 + (lid >> 2);
                    float b0 = bias[r0], b8 = bias[r0 + 8];
#pragma unroll
                    for (int nt = 0; nt < 4; nt++) {
                        int cc0 = wn * 32 + nt * 8 + (lid & 3) * 2;
                        stg[r0 * 65 + cc0]           = acc[mt][nt][0] + b0;
                        stg[r0 * 65 + cc0 + 1]       = acc[mt][nt][1] + b0;
                        stg[(r0 + 8) * 65 + cc0]     = acc[mt][nt][2] + b8;
                        stg[(r0 + 8) * 65 + cc0 + 1] = acc[mt][nt][3] + b8;
                    }
                }
            }
            bar_sync(1, 512);                   // dump complete within group (drains STS)
            bar_arrive(4, THREADS);             // signal stg[r] ready to epilogue warps

            if (r < 2) stage_chunk(sb, r + 1, 0, 0, tid);
        }
    } else {
        // ======================= epilogue warps (128 threads) =======================
        const int t128 = tid - 512;

        // ---- encoder rounds r=0,1 ----
#pragma unroll 1
        for (int r = 0; r < 2; r++) {
            bar_sync(4, THREADS);               // wait stg[r]
#pragma unroll 1
            for (int g = 0; g < 2; g++)
#pragma unroll 1
            for (int sub = 0; sub < 2; sub++) {
                const int t = t128 + sub * 128;
                const int ip = t >> 4;
                const int lane4 = t & 15;
                const int la = lane4 >> 2, lb = lane4 & 3;
#pragma unroll 1
                for (int hl = 0; hl < 2; hl++) {
                    int h = r * 4 + g * 2 + hl;
                    int rowb = g * 128 + hl * 64;
                    const float* qv = lat_s + h * 128 + la * 32;
                    float sc = 0.f;
#pragma unroll
                    for (int d = 0; d < 32; d++)
                        sc += qv[d] * stg[(rowb + 2 * d) * 65 + ip * 4 + lb];
                    float mx = sc;
                    mx = fmaxf(mx, __shfl_xor_sync(FULL, mx, 1, 4));
                    mx = fmaxf(mx, __shfl_xor_sync(FULL, mx, 2, 4));
                    float ex = __expf(sc - mx);
                    float ssum = ex;
                    ssum += __shfl_xor_sync(FULL, ssum, 1, 4);
                    ssum += __shfl_xor_sync(FULL, ssum, 2, 4);
                    float av = ex / ssum;
                    float a4[4];
#pragma unroll
                    for (int s2 = 0; s2 < 4; s2++) a4[s2] = __shfl_sync(FULL, av, la * 4 + s2, 16);

#pragma unroll 1
                    for (int dd = 0; dd < 8; dd++) {
                        int d = lb + 4 * dd;
                        float ltv = lat_s[h * 128 + la * 32 + d];
#pragma unroll
                        for (int s2 = 0; s2 < 4; s2++)
                            ltv += a4[s2] * stg[(rowb + 2 * d + 1) * 65 + ip * 4 + s2];
                        int cch = h * 32 + d;
                        const float* wc = w_s + cch * 24;
                        float s1, c1;
                        __sincosf(ltv * PI_OVER_NB, &s1, &c1);
                        float sM = 0.f, cM = 1.f;
                        float add = wc[12];
#pragma unroll
                        for (int m = 1; m < 12; m++) {
                            float ns = sM * c1 + cM * s1;
                            float nc = cM * c1 - sM * s1;
                            sM = ns; cM = nc;
                            add += ns * wc[m] + nc * wc[12 + m];
                        }
                        lt_h[cch * 66 + ip * 4 + la] = __float2half(ltv + add);
                    }
                }
            }
            bar_arrive(5, THREADS);             // stg[r] free for next dump
        }

        // ---- decoder round ----
        bar_sync(4, THREADS);
#pragma unroll 1
        for (int g = 0; g < 2; g++)
#pragma unroll 1
        for (int sub = 0; sub < 2; sub++) {
            const int t = t128 + sub * 128;
            const int ip = t >> 4;
            const int lane4 = t & 15;
            const int la = lane4 >> 2, lb = lane4 & 3;
#pragma unroll 1
            for (int hl = 0; hl < 4; hl++) {
                int h = g * 4 + hl;
                int rowb = g * 128 + hl * 32;
                float sc = 0.f;
#pragma unroll
                for (int d = 0; d < 32; d++)
                    sc += stg[(rowb + d) * 65 + ip * 4 + la] *
                          __half2float(lt_h[(h * 32 + d) * 66 + ip * 4 + lb]);
                float mx = sc;
                mx = fmaxf(mx, __shfl_xor_sync(FULL, mx, 1, 4));
                mx = fmaxf(mx, __shfl_xor_sync(FULL, mx, 2, 4));
                float ex = __expf(sc - mx);
                float ssum = ex;
                ssum += __shfl_xor_sync(FULL, ssum, 1, 4);
                ssum += __shfl_xor_sync(FULL, ssum, 2, 4);
                float av = ex / ssum;
                float a4[4];
#pragma unroll
                for (int t2 = 0; t2 < 4; t2++) a4[t2] = __shfl_sync(FULL, av, la * 4 + t2, 16);

                int j = ip * 4 + la;
#pragma unroll 1
                for (int dd = 0; dd < 8; dd++) {
                    int d = lb + 4 * dd;
                    int cch = h * 32 + d;
                    float o = 0.f;
#pragma unroll
                    for (int t2 = 0; t2 < 4; t2++)
                        o += a4[t2] * __half2float(lt_h[cch * 66 + ip * 4 + t2]);
                    uint32_t off = (uint32_t)j * 512u +
                                   ((uint32_t)((cch >> 3) ^ (j & 7)) << 4) + (uint32_t)(cch & 7) * 2u;
                    float xr = __half2float(*(__half*)(smem + XTHI + off));
                    og[(size_t)la * 262144 + (size_t)(hp0 + ip) * 256 + cch] = o + xr;
                }
            }
        }
    }
}

extern "C" void kernel_launch(void* const* d_in, const int* in_sizes, int n_in,
                              void* d_out, int out_size)
{
    const float* x       = (const float*)d_in[0];
    const float* weights = (const float*)d_in[1];
    const float* latent  = (const float*)d_in[2];
    const float* enc_w   = (const float*)d_in[3];
    const float* enc_b   = (const float*)d_in[4];
    const float* dec_w   = (const float*)d_in[5];
    const float* dec_b   = (const float*)d_in[6];
    float* out = (float*)d_out;

    prep_kernel<<<(768 * 32 + 255) / 256, 256>>>(enc_w, dec_w);

    cudaFuncSetAttribute(NeuralSpectralBlock1d_4509715661385_kernel,
                         cudaFuncAttributeMaxDynamicSharedMemorySize, (int)SMEM_REQ);
    NeuralSpectralBlock1d_4509715661385_kernel<<<2048, THREADS, SMEM_REQ>>>(
        x, weights, latent, enc_b, dec_b, out);
}

// round 7
// speedup vs baseline: 1.1320x; 1.1320x over previous
#include <cuda_runtime.h>
#include <cuda_fp16.h>
#include <cstdint>

// NeuralSpectralBlock1d: fp16 2-pass mma.sync GEMM + fused SIMT epilogue.
// Round 7: 2 CTAs/SM (256 thr, <=115KB smem each) for cross-CTA phase overlap.
// CTA = 64 columns (16 patches) of one batch. Grid 2048.

#define THREADS 256

// SMEM byte offsets (total 115200 -> 2 CTAs/SM)
#define XTHI 0u          // x^T fp16 [64 n][256 k], 16B-swizzled      (32768)
#define AST  32768u      // weight buf 32768  /  stg fp16 [256][66] = 33792 (aliased)
#define LT   66560u      // lt fp16 [256][64]                          (32768)
#define WS   99328u      // spectral weights fp16 [256][24]            (12288)
#define LAT  111616u     // latent fp16 [1024]                         (2048)
#define EB   113664u     // enc bias fp16 [512]                        (1024)
#define DB   114688u     // dec bias fp16 [256]                        (512)
#define SMEM_REQ 115200u

#define STG_S 66         // stg stride in halves (132B rows, 4B-aligned)
#define LT_S  64         // lt stride in halves

// Pre-split weights: [kchunk 0..7][row 0..767][8 x 16B]; rows 0-511 enc, 512-767 dec.
// 16B cols: logical 0-3 = w_hi(k 0..31 of chunk), 4-7 = w_lo; stored col = logical ^ (row&7).
__device__ uint4 g_wsplit[8][768][8];

__global__ void prep_kernel(const float* __restrict__ enc_w, const float* __restrict__ dec_w) {
    int idx = blockIdx.x * blockDim.x + threadIdx.x;
    if (idx >= 768 * 32) return;
    int row = idx >> 5, c8 = idx & 31;
    const float* src = (row < 512) ? (enc_w + row * 256 + c8 * 8)
                                   : (dec_w + (row - 512) * 256 + c8 * 8);
    union { __half h[8]; uint4 u; } hi, lo;
#pragma unroll
    for (int i = 0; i < 8; i++) {
        float v = src[i];
        hi.h[i] = __float2half(v);
        lo.h[i] = __float2half(v - __half2float(hi.h[i]));
    }
    int chunk = c8 >> 2, lc = c8 & 3;
    g_wsplit[chunk][row][lc ^ (row & 7)]       = hi.u;
    g_wsplit[chunk][row][(lc + 4) ^ (row & 7)] = lo.u;
}

static __device__ __forceinline__ uint32_t smem_u32(const void* p) {
    uint32_t a;
    asm("{ .reg .u64 t; cvta.to.shared.u64 t, %1; cvt.u32.u64 %0, t; }" : "=r"(a) : "l"(p));
    return a;
}
static __device__ __forceinline__ void ldm4(uint32_t* d, uint32_t a) {
    asm volatile("ldmatrix.sync.aligned.m8n8.x4.shared.b16 {%0,%1,%2,%3}, [%4];"
                 : "=r"(d[0]), "=r"(d[1]), "=r"(d[2]), "=r"(d[3]) : "r"(a));
}
static __device__ __forceinline__ void mma16816(float* c, const uint32_t* a, const uint32_t* b) {
    asm volatile("mma.sync.aligned.m16n8k16.row.col.f32.f16.f16.f32 "
                 "{%0,%1,%2,%3}, {%4,%5,%6,%7}, {%8,%9}, {%0,%1,%2,%3};"
                 : "+f"(c[0]), "+f"(c[1]), "+f"(c[2]), "+f"(c[3])
                 : "r"(a[0]), "r"(a[1]), "r"(a[2]), "r"(a[3]), "r"(b[0]), "r"(b[1]));
}

// stage one 32KB weight chunk (rows r*256..+255) into AST (256 threads: 1 row each)
static __device__ __forceinline__ void stage_chunk(uint32_t sb, int r, int chunk, int tid) {
    const uint4* gsrc = &g_wsplit[chunk][r * 256 + tid][0];
    uint32_t dstb = sb + AST + (uint32_t)tid * 128u;
#pragma unroll
    for (int i = 0; i < 8; i++)
        asm volatile("cp.async.cg.shared.global [%0], [%1], 16;"
                     :: "r"(dstb + i * 16), "l"(gsrc + i) : "memory");
    asm volatile("cp.async.commit_group;" ::: "memory");
}

__global__ __launch_bounds__(THREADS, 2)
void NeuralSpectralBlock1d_4509715661385_kernel(
    const float* __restrict__ x, const float* __restrict__ weights,
    const float* __restrict__ latent, const float* __restrict__ enc_b,
    const float* __restrict__ dec_b, float* __restrict__ out)
{
    extern __shared__ char smem[];
    const uint32_t sb = smem_u32(smem);

    __half* stg_h = (__half*)(smem + AST);   // [256][66]
    __half* lt_h  = (__half*)(smem + LT);    // [256][64]
    __half* ws_h  = (__half*)(smem + WS);    // [256][24]
    __half* lat_h = (__half*)(smem + LAT);
    __half* eb_h  = (__half*)(smem + EB);
    __half* db_h  = (__half*)(smem + DB);

    const int tid = threadIdx.x;
    const int wid = tid >> 5, lid = tid & 31;
    const int bx = blockIdx.x;
    const int batch = bx >> 6;
    const int hp0 = (bx & 63) * 16;
    const int h0 = hp0 * 4;
    const float* xg = x + (size_t)batch * 256 * 4096 + h0;
    float* og = out + (size_t)batch * 256 * 4096;

    stage_chunk(sb, 0, 0, tid);   // prefetch round-0 chunk-0 (AST free at start)

    // ---- loads: x tile fp16 swizzled, weights/latent/biases fp16 ----
    for (int idx = tid; idx < 64 * 256; idx += THREADS) {
        int j = idx & 63, c = idx >> 6;
        float v = xg[(size_t)c * 4096 + j];
        uint32_t off = (uint32_t)j * 512u + ((uint32_t)((c >> 3) ^ (j & 7)) << 4) + (uint32_t)(c & 7) * 2u;
        *(__half*)(smem + XTHI + off) = __float2half(v);
    }
    for (int idx = tid; idx < 256 * 24; idx += THREADS) ws_h[idx] = __float2half(weights[idx]);
    for (int idx = tid; idx < 1024; idx += THREADS) lat_h[idx] = __float2half(latent[idx]);
    for (int idx = tid; idx < 512; idx += THREADS) eb_h[idx] = __float2half(enc_b[idx]);
    for (int idx = tid; idx < 256; idx += THREADS) db_h[idx] = __float2half(dec_b[idx]);
    __syncthreads();

    const unsigned FULL = 0xFFFFFFFFu;
    const float PI_OVER_NB = 0.26179938779914943653855361527329f;  // pi/12

    // epilogue lane roles
    const int ip = tid >> 4;
    const int lane4 = tid & 15;
    const int la = lane4 >> 2, lb = lane4 & 3;

    // GEMM warp roles: warp wid owns rows wid*32..+31, all 64 cols
    const int a_row8 = (lid & 7) + ((lid >> 3) & 1) * 8;
    const int a_half = lid >> 4;
    const int b_n8   = (lid & 7) + ((lid >> 4) & 1) * 8;
    const int b_k8   = (lid >> 3) & 1;

    // ================= 3 GEMM rounds: r=0,1 enc; r=2 dec =================
#pragma unroll 1
    for (int r = 0; r < 3; r++) {
        float acc[2][8][4];
#pragma unroll
        for (int mt = 0; mt < 2; mt++)
#pragma unroll
            for (int nt = 0; nt < 8; nt++)
#pragma unroll
                for (int q = 0; q < 4; q++) acc[mt][nt][q] = 0.f;

#pragma unroll 1
        for (int c = 0; c < 8; c++) {
            asm volatile("cp.async.wait_group 0;" ::: "memory");
            __syncthreads();

            const uint32_t ab = sb + AST;
#pragma unroll
            for (int s = 0; s < 2; s++) {
                uint32_t ah[2][4], al[2][4];
#pragma unroll
                for (int mt = 0; mt < 2; mt++) {
                    int row = wid * 32 + mt * 16 + a_row8;
                    int lch = 2 * s + a_half;
                    ldm4(ah[mt], ab + (uint32_t)row * 128u + ((uint32_t)(lch ^ (row & 7)) << 4));
                    int lcl = 4 + 2 * s + a_half;
                    ldm4(al[mt], ab + (uint32_t)row * 128u + ((uint32_t)(lcl ^ (row & 7)) << 4));
                }
                uint32_t bh[4][4];
#pragma unroll
                for (int nb = 0; nb < 4; nb++) {
                    int n = nb * 16 + b_n8;
                    int col = c * 4 + 2 * s + b_k8;
                    uint32_t off = (uint32_t)n * 512u + ((uint32_t)(col ^ (n & 7)) << 4);
                    ldm4(bh[nb], sb + XTHI + off);
                }
#pragma unroll
                for (int mt = 0; mt < 2; mt++)
#pragma unroll
                    for (int nt = 0; nt < 8; nt++) {
                        const uint32_t* B0 = &bh[nt >> 1][(nt & 1) * 2];
                        mma16816(acc[mt][nt], ah[mt], B0);   // w_hi * x
                        mma16816(acc[mt][nt], al[mt], B0);   // w_lo * x
                    }
            }
            __syncthreads();                      // all warps done reading AST
            if (c < 7) stage_chunk(sb, r, c + 1, tid);
        }

        // ---- dump acc -> stg fp16 (+bias); AST reused as stg ----
        {
            const __half* bias = (r < 2) ? (eb_h + r * 256) : db_h;
            __half2* stg2 = (__half2*)stg_h;
#pragma unroll
            for (int mt = 0; mt < 2; mt++) {
                int r0 = wid * 32 + mt * 16 + (lid >> 2);
                float b0 = __half2float(bias[r0]), b8 = __half2float(bias[r0 + 8]);
#pragma unroll
                for (int nt = 0; nt < 8; nt++) {
                    int cc0 = nt * 8 + (lid & 3) * 2;
                    stg2[r0 * (STG_S / 2) + (cc0 >> 1)] =
                        __floats2half2_rn(acc[mt][nt][0] + b0, acc[mt][nt][1] + b0);
                    stg2[(r0 + 8) * (STG_S / 2) + (cc0 >> 1)] =
                        __floats2half2_rn(acc[mt][nt][2] + b8, acc[mt][nt][3] + b8);
                }
            }
        }
        __syncthreads();

        if (r < 2) {
            // ===== encoder epilogue: 4 heads (g-loop over halves) =====
#pragma unroll 1
            for (int g = 0; g < 2; g++)
#pragma unroll 1
            for (int hl = 0; hl < 2; hl++) {
                int h = r * 4 + g * 2 + hl;
                int rowb = g * 128 + hl * 64;
                float sc = 0.f;
#pragma unroll
                for (int d = 0; d < 32; d++)
                    sc += __half2float(lat_h[h * 128 + la * 32 + d]) *
                          __half2float(stg_h[(rowb + 2 * d) * STG_S + ip * 4 + lb]);
                float mx = sc;
                mx = fmaxf(mx, __shfl_xor_sync(FULL, mx, 1, 4));
                mx = fmaxf(mx, __shfl_xor_sync(FULL, mx, 2, 4));
                float ex = __expf(sc - mx);
                float ssum = ex;
                ssum += __shfl_xor_sync(FULL, ssum, 1, 4);
                ssum += __shfl_xor_sync(FULL, ssum, 2, 4);
                float av = ex / ssum;
                float a4[4];
#pragma unroll
                for (int s2 = 0; s2 < 4; s2++) a4[s2] = __shfl_sync(FULL, av, la * 4 + s2, 16);

#pragma unroll 1
                for (int dd = 0; dd < 8; dd++) {
                    int d = lb + 4 * dd;
                    float ltv = __half2float(lat_h[h * 128 + la * 32 + d]);
#pragma unroll
                    for (int s2 = 0; s2 < 4; s2++)
                        ltv += a4[s2] * __half2float(stg_h[(rowb + 2 * d + 1) * STG_S + ip * 4 + s2]);
                    int cch = h * 32 + d;
                    const __half* wc = ws_h + cch * 24;
                    float s1, c1;
                    __sincosf(ltv * PI_OVER_NB, &s1, &c1);
                    float sM = 0.f, cM = 1.f;
                    float add = __half2float(wc[12]);
#pragma unroll
                    for (int m = 1; m < 12; m++) {
                        float ns = sM * c1 + cM * s1;
                        float nc = cM * c1 - sM * s1;
                        sM = ns; cM = nc;
                        add += ns * __half2float(wc[m]) + nc * __half2float(wc[12 + m]);
                    }
                    lt_h[cch * LT_S + ip * 4 + la] = __float2half(ltv + add);
                }
            }
        } else {
            // ===== decoder epilogue: 8 heads (g-loop over halves) =====
#pragma unroll 1
            for (int g = 0; g < 2; g++)
#pragma unroll 1
            for (int hl = 0; hl < 4; hl++) {
                int h = g * 4 + hl;
                int rowb = g * 128 + hl * 32;
                float sc = 0.f;
#pragma unroll
                for (int d = 0; d < 32; d++)
                    sc += __half2float(stg_h[(rowb + d) * STG_S + ip * 4 + la]) *
                          __half2float(lt_h[(h * 32 + d) * LT_S + ip * 4 + lb]);
                float mx = sc;
                mx = fmaxf(mx, __shfl_xor_sync(FULL, mx, 1, 4));
                mx = fmaxf(mx, __shfl_xor_sync(FULL, mx, 2, 4));
                float ex = __expf(sc - mx);
                float ssum = ex;
                ssum += __shfl_xor_sync(FULL, ssum, 1, 4);
                ssum += __shfl_xor_sync(FULL, ssum, 2, 4);
                float av = ex / ssum;
                float a4[4];
#pragma unroll
                for (int t2 = 0; t2 < 4; t2++) a4[t2] = __shfl_sync(FULL, av, la * 4 + t2, 16);

                int j = ip * 4 + la;
#pragma unroll 1
                for (int dd = 0; dd < 8; dd++) {
                    int d = lb + 4 * dd;
                    int cch = h * 32 + d;
                    float o = 0.f;
#pragma unroll
                    for (int t2 = 0; t2 < 4; t2++)
                        o += a4[t2] * __half2float(lt_h[cch * LT_S + ip * 4 + t2]);
                    uint32_t off = (uint32_t)j * 512u +
                                   ((uint32_t)((cch >> 3) ^ (j & 7)) << 4) + (uint32_t)(cch & 7) * 2u;
                    float xr = __half2float(*(__half*)(smem + XTHI + off));
                    og[(size_t)la * 262144 + (size_t)(hp0 + ip) * 256 + cch] = o + xr;
                }
            }
        }
        __syncthreads();                         // stg (AST) free for next round staging

        if (r < 2) stage_chunk(sb, r + 1, 0, tid);
    }
}

extern "C" void kernel_launch(void* const* d_in, const int* in_sizes, int n_in,
                              void* d_out, int out_size)
{
    const float* x       = (const float*)d_in[0];
    const float* weights = (const float*)d_in[1];
    const float* latent  = (const float*)d_in[2];
    const float* enc_w   = (const float*)d_in[3];
    const float* enc_b   = (const float*)d_in[4];
    const float* dec_w   = (const float*)d_in[5];
    const float* dec_b   = (const float*)d_in[6];
    float* out = (float*)d_out;

    prep_kernel<<<(768 * 32 + 255) / 256, 256>>>(enc_w, dec_w);

    cudaFuncSetAttribute(NeuralSpectralBlock1d_4509715661385_kernel,
                         cudaFuncAttributeMaxDynamicSharedMemorySize, (int)SMEM_REQ);
    NeuralSpectralBlock1d_4509715661385_kernel<<<2048, THREADS, SMEM_REQ>>>(
        x, weights, latent, enc_b, dec_b, out);
}

// round 8
// speedup vs baseline: 1.5870x; 1.4020x over previous
#include <cuda_runtime.h>
#include <cuda_fp16.h>
#include <cstdint>

// NeuralSpectralBlock1d: fp16 2-pass mma.sync GEMM, ping/pong weight fetch,
// transposed (pos-major) epilogue staging, coalesced stores. 2 CTAs/SM.
// CTA = 64 columns (16 patches) of one batch. Grid 2048, 256 threads.

#define THREADS 256

// SMEM layout (total 114176 B -> 2 CTAs/SM)
#define XTHI 0u          // x^T fp16 [64 j][256 k], 16B-swizzled       (32768)
#define AST  32768u      // GEMM: ping/pong 2x16384 ; epi: stg_t [64 pos][528B] (33792)
#define LTT  66560u      // lt_t fp16 [64 tok][528B]                    (33792)
#define WS   100352u     // spectral weights fp16 [256][24]             (12288)
#define EB   112640u     // enc bias fp16 [512]                         (1024)
#define DB   113664u     // dec bias fp16 [256]                         (512)
#define SMEM_REQ 114176u

#define TSB 528u         // transposed row stride in bytes (264 halves)

// Pre-split weights: [kchunk 0..15][row 0..767][4 x 16B]; rows 0-511 enc, 512-767 dec.
// Chunk = 16 k. 16B cols: logical 0,1 = w_hi (k0-7, k8-15), 2,3 = w_lo.
// stored col = logical ^ ((row>>1)&3)  -> conflict-free ldmatrix on 64B rows.
__device__ uint4 g_wsplit[16][768][4];

__global__ void prep_kernel(const float* __restrict__ enc_w, const float* __restrict__ dec_w) {
    int idx = blockIdx.x * blockDim.x + threadIdx.x;
    if (idx >= 768 * 32) return;
    int row = idx >> 5, c8 = idx & 31;           // c8: 8-k group
    const float* src = (row < 512) ? (enc_w + row * 256 + c8 * 8)
                                   : (dec_w + (row - 512) * 256 + c8 * 8);
    union { __half h[8]; uint4 u; } hi, lo;
#pragma unroll
    for (int i = 0; i < 8; i++) {
        float v = src[i];
        hi.h[i] = __float2half(v);
        lo.h[i] = __float2half(v - __half2float(hi.h[i]));
    }
    int chunk = c8 >> 1, lc = c8 & 1;
    int sw = (row >> 1) & 3;
    g_wsplit[chunk][row][lc ^ sw]       = hi.u;
    g_wsplit[chunk][row][(2 + lc) ^ sw] = lo.u;
}

static __device__ __forceinline__ uint32_t smem_u32(const void* p) {
    uint32_t a;
    asm("{ .reg .u64 t; cvta.to.shared.u64 t, %1; cvt.u32.u64 %0, t; }" : "=r"(a) : "l"(p));
    return a;
}
static __device__ __forceinline__ void ldm4(uint32_t* d, uint32_t a) {
    asm volatile("ldmatrix.sync.aligned.m8n8.x4.shared.b16 {%0,%1,%2,%3}, [%4];"
                 : "=r"(d[0]), "=r"(d[1]), "=r"(d[2]), "=r"(d[3]) : "r"(a));
}
static __device__ __forceinline__ void mma16816(float* c, const uint32_t* a, const uint32_t* b) {
    asm volatile("mma.sync.aligned.m16n8k16.row.col.f32.f16.f16.f32 "
                 "{%0,%1,%2,%3}, {%4,%5,%6,%7}, {%8,%9}, {%0,%1,%2,%3};"
                 : "+f"(c[0]), "+f"(c[1]), "+f"(c[2]), "+f"(c[3])
                 : "r"(a[0]), "r"(a[1]), "r"(a[2]), "r"(a[3]), "r"(b[0]), "r"(b[1]));
}

// stage one 16KB sub-chunk (rows r*256..+255, k-chunk `chunk`) into buffer `buf`
static __device__ __forceinline__ void stage16(uint32_t sb, int r, int chunk, int buf, int tid) {
    const uint4* g = &g_wsplit[chunk][r * 256 + tid][0];
    uint32_t d = sb + AST + (uint32_t)buf * 16384u + (uint32_t)tid * 64u;
#pragma unroll
    for (int i = 0; i < 4; i++)
        asm volatile("cp.async.cg.shared.global [%0], [%1], 16;"
                     :: "r"(d + i * 16), "l"(g + i) : "memory");
    asm volatile("cp.async.commit_group;" ::: "memory");
}

__global__ __launch_bounds__(THREADS, 2)
void NeuralSpectralBlock1d_4509715661385_kernel(
    const float* __restrict__ x, const float* __restrict__ weights,
    const float* __restrict__ latent, const float* __restrict__ enc_b,
    const float* __restrict__ dec_b, float* __restrict__ out)
{
    extern __shared__ char smem[];
    const uint32_t sb = smem_u32(smem);

    __half* ws_h = (__half*)(smem + WS);
    __half* eb_h = (__half*)(smem + EB);
    __half* db_h = (__half*)(smem + DB);

    const int tid = threadIdx.x;
    const int wid = tid >> 5, lid = tid & 31;
    const int bx = blockIdx.x;
    const int batch = bx >> 6;
    const int hp0 = (bx & 63) * 16;
    const int h0 = hp0 * 4;
    const float* xg = x + (size_t)batch * 256 * 4096 + h0;
    float* og = out + (size_t)batch * 256 * 4096;

    stage16(sb, 0, 0, 0, tid);   // prefetch round-0 sub-chunk 0

    // ---- loads: x tile fp16 swizzled, spectral weights, biases ----
    for (int idx = tid; idx < 64 * 256; idx += THREADS) {
        int j = idx & 63, c = idx >> 6;
        float v = xg[(size_t)c * 4096 + j];
        uint32_t off = (uint32_t)j * 512u + ((uint32_t)((c >> 3) ^ (j & 7)) << 4) + (uint32_t)(c & 7) * 2u;
        *(__half*)(smem + XTHI + off) = __float2half(v);
    }
    for (int idx = tid; idx < 256 * 24; idx += THREADS) ws_h[idx] = __float2half(weights[idx]);
    for (int idx = tid; idx < 512; idx += THREADS) eb_h[idx] = __float2half(enc_b[idx]);
    for (int idx = tid; idx < 256; idx += THREADS) db_h[idx] = __float2half(dec_b[idx]);
    __syncthreads();

    const unsigned FULL = 0xFFFFFFFFu;
    const float PI_OVER_NB = 0.26179938779914943653855361527329f;  // pi/12

    // epilogue lane roles
    const int ip = tid >> 4;
    const int lane4 = tid & 15;
    const int la = lane4 >> 2, lb = lane4 & 3;

    // GEMM roles: warp wid owns rows wid*32..+31, all 64 cols
    const uint32_t a_row8 = (uint32_t)((lid & 7) + ((lid >> 3) & 1) * 8);
    const uint32_t a_half = (uint32_t)(lid >> 4);
    const int b_n8   = (lid & 7) + ((lid >> 4) & 1) * 8;
    const int b_k8   = (lid >> 3) & 1;

    // ================= 3 GEMM rounds: r=0,1 enc; r=2 dec =================
#pragma unroll 1
    for (int r = 0; r < 3; r++) {
        float acc[2][8][4];
#pragma unroll
        for (int mt = 0; mt < 2; mt++)
#pragma unroll
            for (int nt = 0; nt < 8; nt++)
#pragma unroll
                for (int q = 0; q < 4; q++) acc[mt][nt][q] = 0.f;

#pragma unroll 1
        for (int c = 0; c < 16; c++) {
            asm volatile("cp.async.wait_group 0;" ::: "memory");
            __syncthreads();
            if (c < 15) stage16(sb, r, c + 1, (c + 1) & 1, tid);   // overlaps compute below

            const uint32_t ab = sb + AST + (uint32_t)(c & 1) * 16384u;
            uint32_t ah[2][4], al[2][4];
#pragma unroll
            for (int mt = 0; mt < 2; mt++) {
                int rowm = wid * 32 + mt * 16 + (int)a_row8;
                uint32_t rb = ab + (uint32_t)rowm * 64u;
                uint32_t sw4 = (uint32_t)((rowm >> 1) & 3);
                ldm4(ah[mt], rb + ((a_half ^ sw4) << 4));
                ldm4(al[mt], rb + (((2u + a_half) ^ sw4) << 4));
            }
            uint32_t bh[4][4];
#pragma unroll
            for (int nb = 0; nb < 4; nb++) {
                int n = nb * 16 + b_n8;
                int col = c * 2 + b_k8;
                ldm4(bh[nb], sb + XTHI + (uint32_t)n * 512u + ((uint32_t)(col ^ (n & 7)) << 4));
            }
#pragma unroll
            for (int mt = 0; mt < 2; mt++)
#pragma unroll
                for (int nt = 0; nt < 8; nt++) {
                    const uint32_t* B0 = &bh[nt >> 1][(nt & 1) * 2];
                    mma16816(acc[mt][nt], ah[mt], B0);   // w_hi * x
                    mma16816(acc[mt][nt], al[mt], B0);   // w_lo * x
                }
            __syncthreads();                    // reads done before next stage overwrite
        }

        // ---- dump acc -> stg_t[pos][ch] fp16 (+bias), transposed ----
        {
            const __half* bias = (r < 2) ? (eb_h + r * 256) : db_h;
            __half* st = (__half*)(smem + AST);
#pragma unroll
            for (int mt = 0; mt < 2; mt++) {
                int r0 = wid * 32 + mt * 16 + (lid >> 2);
                float b0 = __half2float(bias[r0]), b8 = __half2float(bias[r0 + 8]);
#pragma unroll
                for (int nt = 0; nt < 8; nt++) {
                    int cc0 = nt * 8 + (lid & 3) * 2;
                    st[cc0 * 264 + r0]           = __float2half(acc[mt][nt][0] + b0);
                    st[(cc0 + 1) * 264 + r0]     = __float2half(acc[mt][nt][1] + b0);
                    st[cc0 * 264 + r0 + 8]       = __float2half(acc[mt][nt][2] + b8);
                    st[(cc0 + 1) * 264 + r0 + 8] = __float2half(acc[mt][nt][3] + b8);
                }
            }
        }
        __syncthreads();

        if (r < 2) {
            // ===== encoder epilogue (heads r*4 .. r*4+3) =====
#pragma unroll 1
            for (int hl4 = 0; hl4 < 4; hl4++) {
                int h = r * 4 + hl4;
                const float* qg = latent + h * 128 + la * 32;
                const char* srow = smem + AST + (uint32_t)(ip * 4 + lb) * TSB + (uint32_t)hl4 * 128u;
                float sc = 0.f;
                float qs[8];                     // q value at d = lb + 4*i
#pragma unroll
                for (int i = 0; i < 8; i++) {
                    uint4 u = *(const uint4*)(srow + i * 16);   // (k,v) pairs d=4i..4i+3
                    float4 q4 = *(const float4*)(qg + i * 4);
                    const __half2* hp = (const __half2*)&u;
                    float2 p0 = __half22float2(hp[0]);
                    float2 p1 = __half22float2(hp[1]);
                    float2 p2 = __half22float2(hp[2]);
                    float2 p3 = __half22float2(hp[3]);
                    sc += q4.x * p0.x + q4.y * p1.x + q4.z * p2.x + q4.w * p3.x;
                    qs[i] = (lb & 2) ? ((lb & 1) ? q4.w : q4.z) : ((lb & 1) ? q4.y : q4.x);
                }
                float mx = sc;
                mx = fmaxf(mx, __shfl_xor_sync(FULL, mx, 1, 4));
                mx = fmaxf(mx, __shfl_xor_sync(FULL, mx, 2, 4));
                float ex = __expf(sc - mx);
                float ssum = ex;
                ssum += __shfl_xor_sync(FULL, ssum, 1, 4);
                ssum += __shfl_xor_sync(FULL, ssum, 2, 4);
                float av = ex / ssum;
                float a4[4];
#pragma unroll
                for (int s2 = 0; s2 < 4; s2++) a4[s2] = __shfl_sync(FULL, av, la * 4 + s2, 16);

                // v stage: thread (ip, tt=la, g=lb) handles d = lb + 4*dd
#pragma unroll 1
                for (int dd = 0; dd < 8; dd++) {
                    int d = lb + 4 * dd;
                    float ltv = qs[dd];          // q residual (lat value at this d)
#pragma unroll
                    for (int s2 = 0; s2 < 4; s2++)
                        ltv += a4[s2] * __half2float(*(const __half*)(smem + AST +
                                   (uint32_t)(ip * 4 + s2) * TSB + (uint32_t)(hl4 * 128 + 4 * d + 2)));
                    int cch = h * 32 + d;
                    const __half* wc = ws_h + cch * 24;
                    float s1, c1;
                    __sincosf(ltv * PI_OVER_NB, &s1, &c1);
                    float sM = 0.f, cM = 1.f;
                    float add = __half2float(wc[12]);
#pragma unroll
                    for (int m = 1; m < 12; m++) {
                        float ns = sM * c1 + cM * s1;
                        float nc = cM * c1 - sM * s1;
                        sM = ns; cM = nc;
                        add += ns * __half2float(wc[m]) + nc * __half2float(wc[12 + m]);
                    }
                    *(__half*)(smem + LTT + (uint32_t)(ip * 4 + la) * TSB + (uint32_t)cch * 2u) =
                        __float2half(ltv + add);
                }
            }
        } else {
            // ===== decoder epilogue (heads 0..7) =====
#pragma unroll 1
            for (int h = 0; h < 8; h++) {
                const char* dqp = smem + AST + (uint32_t)(ip * 4 + la) * TSB + (uint32_t)h * 64u;
                const char* ltp = smem + LTT + (uint32_t)(ip * 4 + lb) * TSB + (uint32_t)h * 64u;
                float sc = 0.f;
#pragma unroll
                for (int i = 0; i < 4; i++) {
                    uint4 ua = *(const uint4*)(dqp + i * 16);
                    uint4 ub = *(const uint4*)(ltp + i * 16);
                    const __half2* pa = (const __half2*)&ua;
                    const __half2* pb = (const __half2*)&ub;
#pragma unroll
                    for (int j2 = 0; j2 < 4; j2++) {
                        float2 fa = __half22float2(pa[j2]);
                        float2 fb = __half22float2(pb[j2]);
                        sc += fa.x * fb.x + fa.y * fb.y;
                    }
                }
                float mx = sc;
                mx = fmaxf(mx, __shfl_xor_sync(FULL, mx, 1, 4));
                mx = fmaxf(mx, __shfl_xor_sync(FULL, mx, 2, 4));
                float ex = __expf(sc - mx);
                float ssum = ex;
                ssum += __shfl_xor_sync(FULL, ssum, 1, 4);
                ssum += __shfl_xor_sync(FULL, ssum, 2, 4);
                float av = ex / ssum;
                float a4[4];
#pragma unroll
                for (int t2 = 0; t2 < 4; t2++) a4[t2] = __shfl_sync(FULL, av, la * 4 + t2, 16);

                // v stage: thread (ip, pos=la, cg=lb) -> ch = h*32 + lb*8 .. +7 (coalesced)
                float o[8];
#pragma unroll
                for (int i = 0; i < 8; i++) o[i] = 0.f;
#pragma unroll
                for (int t2 = 0; t2 < 4; t2++) {
                    uint4 lv = *(const uint4*)(smem + LTT + (uint32_t)(ip * 4 + t2) * TSB +
                                               (uint32_t)h * 64u + (uint32_t)lb * 16u);
                    const __half2* hp = (const __half2*)&lv;
                    float a = a4[t2];
#pragma unroll
                    for (int j2 = 0; j2 < 4; j2++) {
                        float2 f = __half22float2(hp[j2]);
                        o[2 * j2]     += a * f.x;
                        o[2 * j2 + 1] += a * f.y;
                    }
                }
                int j = ip * 4 + la;
                uint32_t xoff = (uint32_t)j * 512u + ((uint32_t)((h * 4 + lb) ^ (j & 7)) << 4);
                uint4 xv = *(const uint4*)(smem + XTHI + xoff);
                const __half2* xp = (const __half2*)&xv;
                float4 o0, o1;
                {
                    float2 f0 = __half22float2(xp[0]);
                    float2 f1 = __half22float2(xp[1]);
                    float2 f2 = __half22float2(xp[2]);
                    float2 f3 = __half22float2(xp[3]);
                    o0.x = o[0] + f0.x; o0.y = o[1] + f0.y;
                    o0.z = o[2] + f1.x; o0.w = o[3] + f1.y;
                    o1.x = o[4] + f2.x; o1.y = o[5] + f2.y;
                    o1.z = o[6] + f3.x; o1.w = o[7] + f3.y;
                }
                float* ob = og + (size_t)la * 262144 + (size_t)(hp0 + ip) * 256 + h * 32 + lb * 8;
                *(float4*)ob = o0;
                *(float4*)(ob + 4) = o1;
            }
        }
        __syncthreads();                         // stg_t (AST) free for next round staging

        if (r < 2) stage16(sb, r + 1, 0, 0, tid);
    }
}

extern "C" void kernel_launch(void* const* d_in, const int* in_sizes, int n_in,
                              void* d_out, int out_size)
{
    const float* x       = (const float*)d_in[0];
    const float* weights = (const float*)d_in[1];
    const float* latent  = (const float*)d_in[2];
    const float* enc_w   = (const float*)d_in[3];
    const float* enc_b   = (const float*)d_in[4];
    const float* dec_w   = (const float*)d_in[5];
    const float* dec_b   = (const float*)d_in[6];
    float* out = (float*)d_out;

    prep_kernel<<<(768 * 32 + 255) / 256, 256>>>(enc_w, dec_w);

    cudaFuncSetAttribute(NeuralSpectralBlock1d_4509715661385_kernel,
                         cudaFuncAttributeMaxDynamicSharedMemorySize, (int)SMEM_REQ);
    NeuralSpectralBlock1d_4509715661385_kernel<<<2048, THREADS, SMEM_REQ>>>(
        x, weights, latent, enc_b, dec_b, out);
}

// round 9
// speedup vs baseline: 2.0794x; 1.3103x over previous
#include <cuda_runtime.h>
#include <cuda_fp16.h>
#include <cstdint>

// NeuralSpectralBlock1d: single-pass fp16 mma.sync GEMM (x and w both fp16),
// ping/pong 8KB weight fetch, transposed epilogue staging, coalesced stores.
// 2 CTAs/SM. CTA = 64 columns (16 patches) of one batch. Grid 2048, 256 threads.

#define THREADS 256

// SMEM layout (total 114176 B -> 2 CTAs/SM)
#define XTHI 0u          // x^T fp16 [64 j][256 k], 16B-swizzled       (32768)
#define AST  32768u      // GEMM: ping/pong 2x8192 ; epi: stg_t [64 pos][528B] (33792)
#define LTT  66560u      // lt_t fp16 [64 tok][528B]                    (33792)
#define WS   100352u     // spectral weights fp16 [256][24]             (12288)
#define EB   112640u     // enc bias fp16 [512]                         (1024)
#define DB   113664u     // dec bias fp16 [256]                         (512)
#define SMEM_REQ 114176u

#define TSB 528u         // transposed row stride in bytes (264 halves)

// fp16 weights: [kchunk 0..15][row 0..767][2 x 16B]; rows 0-511 enc, 512-767 dec.
// Chunk = 16 k. 16B cols: logical 0 = k0-7, 1 = k8-15; stored col = logical ^ ((row>>2)&1).
__device__ uint4 g_w16[16][768][2];

__global__ void prep_kernel(const float* __restrict__ enc_w, const float* __restrict__ dec_w) {
    int idx = blockIdx.x * blockDim.x + threadIdx.x;
    if (idx >= 768 * 32) return;
    int row = idx >> 5, c8 = idx & 31;           // c8: 8-k group
    const float* src = (row < 512) ? (enc_w + row * 256 + c8 * 8)
                                   : (dec_w + (row - 512) * 256 + c8 * 8);
    union { __half h[8]; uint4 u; } hi;
#pragma unroll
    for (int i = 0; i < 8; i++) hi.h[i] = __float2half(src[i]);
    int chunk = c8 >> 1, lc = c8 & 1;
    g_w16[chunk][row][lc ^ ((row >> 2) & 1)] = hi.u;
}

static __device__ __forceinline__ uint32_t smem_u32(const void* p) {
    uint32_t a;
    asm("{ .reg .u64 t; cvta.to.shared.u64 t, %1; cvt.u32.u64 %0, t; }" : "=r"(a) : "l"(p));
    return a;
}
static __device__ __forceinline__ void ldm4(uint32_t* d, uint32_t a) {
    asm volatile("ldmatrix.sync.aligned.m8n8.x4.shared.b16 {%0,%1,%2,%3}, [%4];"
                 : "=r"(d[0]), "=r"(d[1]), "=r"(d[2]), "=r"(d[3]) : "r"(a));
}
static __device__ __forceinline__ void mma16816(float* c, const uint32_t* a, const uint32_t* b) {
    asm volatile("mma.sync.aligned.m16n8k16.row.col.f32.f16.f16.f32 "
                 "{%0,%1,%2,%3}, {%4,%5,%6,%7}, {%8,%9}, {%0,%1,%2,%3};"
                 : "+f"(c[0]), "+f"(c[1]), "+f"(c[2]), "+f"(c[3])
                 : "r"(a[0]), "r"(a[1]), "r"(a[2]), "r"(a[3]), "r"(b[0]), "r"(b[1]));
}

// stage one 8KB sub-chunk (rows r*256..+255, k-chunk `chunk`) into buffer `buf`
static __device__ __forceinline__ void stage8(uint32_t sb, int r, int chunk, int buf, int tid) {
    const uint4* g = &g_w16[chunk][r * 256 + tid][0];
    uint32_t d = sb + AST + (uint32_t)buf * 8192u + (uint32_t)tid * 32u;
    asm volatile("cp.async.cg.shared.global [%0], [%1], 16;" :: "r"(d), "l"(g) : "memory");
    asm volatile("cp.async.cg.shared.global [%0], [%1], 16;" :: "r"(d + 16), "l"(g + 1) : "memory");
    asm volatile("cp.async.commit_group;" ::: "memory");
}

__global__ __launch_bounds__(THREADS, 2)
void NeuralSpectralBlock1d_4509715661385_kernel(
    const float* __restrict__ x, const float* __restrict__ weights,
    const float* __restrict__ latent, const float* __restrict__ enc_b,
    const float* __restrict__ dec_b, float* __restrict__ out)
{
    extern __shared__ char smem[];
    const uint32_t sb = smem_u32(smem);

    __half* ws_h = (__half*)(smem + WS);
    __half* eb_h = (__half*)(smem + EB);
    __half* db_h = (__half*)(smem + DB);

    const int tid = threadIdx.x;
    const int wid = tid >> 5, lid = tid & 31;
    const int bx = blockIdx.x;
    const int batch = bx >> 6;
    const int hp0 = (bx & 63) * 16;
    const int h0 = hp0 * 4;
    const float* xg = x + (size_t)batch * 256 * 4096 + h0;
    float* og = out + (size_t)batch * 256 * 4096;

    stage8(sb, 0, 0, 0, tid);    // prefetch round-0 sub-chunk 0

    // ---- loads: x tile fp16 swizzled, spectral weights, biases ----
    for (int idx = tid; idx < 64 * 256; idx += THREADS) {
        int j = idx & 63, c = idx >> 6;
        float v = xg[(size_t)c * 4096 + j];
        uint32_t off = (uint32_t)j * 512u + ((uint32_t)((c >> 3) ^ (j & 7)) << 4) + (uint32_t)(c & 7) * 2u;
        *(__half*)(smem + XTHI + off) = __float2half(v);
    }
    for (int idx = tid; idx < 256 * 24; idx += THREADS) ws_h[idx] = __float2half(weights[idx]);
    for (int idx = tid; idx < 512; idx += THREADS) eb_h[idx] = __float2half(enc_b[idx]);
    for (int idx = tid; idx < 256; idx += THREADS) db_h[idx] = __float2half(dec_b[idx]);
    __syncthreads();

    const unsigned FULL = 0xFFFFFFFFu;
    const float PI_OVER_NB = 0.26179938779914943653855361527329f;  // pi/12

    // epilogue lane roles
    const int ip = tid >> 4;
    const int lane4 = tid & 15;
    const int la = lane4 >> 2, lb = lane4 & 3;

    // GEMM roles: warp wid owns rows wid*32..+31, all 64 cols
    const uint32_t a_row8 = (uint32_t)((lid & 7) + ((lid >> 3) & 1) * 8);
    const uint32_t a_half = (uint32_t)(lid >> 4);
    const int b_n8   = (lid & 7) + ((lid >> 4) & 1) * 8;
    const int b_k8   = (lid >> 3) & 1;

    // ================= 3 GEMM rounds: r=0,1 enc; r=2 dec =================
#pragma unroll 1
    for (int r = 0; r < 3; r++) {
        float acc[2][8][4];
#pragma unroll
        for (int mt = 0; mt < 2; mt++)
#pragma unroll
            for (int nt = 0; nt < 8; nt++)
#pragma unroll
                for (int q = 0; q < 4; q++) acc[mt][nt][q] = 0.f;

#pragma unroll 1
        for (int c = 0; c < 16; c++) {
            asm volatile("cp.async.wait_group 0;" ::: "memory");
            __syncthreads();
            if (c < 15) stage8(sb, r, c + 1, (c + 1) & 1, tid);    // overlaps compute below

            const uint32_t ab = sb + AST + (uint32_t)(c & 1) * 8192u;
            uint32_t ah[2][4];
#pragma unroll
            for (int mt = 0; mt < 2; mt++) {
                int rowm = wid * 32 + mt * 16 + (int)a_row8;
                uint32_t sw1 = (uint32_t)((rowm >> 2) & 1);
                ldm4(ah[mt], ab + (uint32_t)rowm * 32u + ((a_half ^ sw1) << 4));
            }
            uint32_t bh[4][4];
#pragma unroll
            for (int nb = 0; nb < 4; nb++) {
                int n = nb * 16 + b_n8;
                int col = c * 2 + b_k8;
                ldm4(bh[nb], sb + XTHI + (uint32_t)n * 512u + ((uint32_t)(col ^ (n & 7)) << 4));
            }
#pragma unroll
            for (int mt = 0; mt < 2; mt++)
#pragma unroll
                for (int nt = 0; nt < 8; nt++)
                    mma16816(acc[mt][nt], ah[mt], &bh[nt >> 1][(nt & 1) * 2]);
            __syncthreads();                     // reads done before next stage overwrite
        }

        // ---- dump acc -> stg_t[pos][ch] fp16 (+bias), transposed ----
        {
            const __half* bias = (r < 2) ? (eb_h + r * 256) : db_h;
            __half* st = (__half*)(smem + AST);
#pragma unroll
            for (int mt = 0; mt < 2; mt++) {
                int r0 = wid * 32 + mt * 16 + (lid >> 2);
                float b0 = __half2float(bias[r0]), b8 = __half2float(bias[r0 + 8]);
#pragma unroll
                for (int nt = 0; nt < 8; nt++) {
                    int cc0 = nt * 8 + (lid & 3) * 2;
                    st[cc0 * 264 + r0]           = __float2half(acc[mt][nt][0] + b0);
                    st[(cc0 + 1) * 264 + r0]     = __float2half(acc[mt][nt][1] + b0);
                    st[cc0 * 264 + r0 + 8]       = __float2half(acc[mt][nt][2] + b8);
                    st[(cc0 + 1) * 264 + r0 + 8] = __float2half(acc[mt][nt][3] + b8);
                }
            }
        }
        __syncthreads();

        if (r < 2) {
            // ===== encoder epilogue (heads r*4 .. r*4+3) =====
#pragma unroll 1
            for (int hl4 = 0; hl4 < 4; hl4++) {
                int h = r * 4 + hl4;
                const float* qg = latent + h * 128 + la * 32;
                const char* srow = smem + AST + (uint32_t)(ip * 4 + lb) * TSB + (uint32_t)hl4 * 128u;
                float sc = 0.f;
                float qs[8];                     // q value at d = lb + 4*i
#pragma unroll
                for (int i = 0; i < 8; i++) {
                    uint4 u = *(const uint4*)(srow + i * 16);   // (k,v) pairs d=4i..4i+3
                    float4 q4 = *(const float4*)(qg + i * 4);
                    const __half2* hp = (const __half2*)&u;
                    float2 p0 = __half22float2(hp[0]);
                    float2 p1 = __half22float2(hp[1]);
                    float2 p2 = __half22float2(hp[2]);
                    float2 p3 = __half22float2(hp[3]);
                    sc += q4.x * p0.x + q4.y * p1.x + q4.z * p2.x + q4.w * p3.x;
                    qs[i] = (lb & 2) ? ((lb & 1) ? q4.w : q4.z) : ((lb & 1) ? q4.y : q4.x);
                }
                float mx = sc;
                mx = fmaxf(mx, __shfl_xor_sync(FULL, mx, 1, 4));
                mx = fmaxf(mx, __shfl_xor_sync(FULL, mx, 2, 4));
                float ex = __expf(sc - mx);
                float ssum = ex;
                ssum += __shfl_xor_sync(FULL, ssum, 1, 4);
                ssum += __shfl_xor_sync(FULL, ssum, 2, 4);
                float av = ex / ssum;
                float a4[4];
#pragma unroll
                for (int s2 = 0; s2 < 4; s2++) a4[s2] = __shfl_sync(FULL, av, la * 4 + s2, 16);

                // v stage: thread (ip, tt=la, g=lb) handles d = lb + 4*dd
#pragma unroll 1
                for (int dd = 0; dd < 8; dd++) {
                    int d = lb + 4 * dd;
                    float ltv = qs[dd];          // q residual (lat value at this d)
#pragma unroll
                    for (int s2 = 0; s2 < 4; s2++)
                        ltv += a4[s2] * __half2float(*(const __half*)(smem + AST +
                                   (uint32_t)(ip * 4 + s2) * TSB + (uint32_t)(hl4 * 128 + 4 * d + 2)));
                    int cch = h * 32 + d;
                    const __half* wc = ws_h + cch * 24;
                    float s1, c1;
                    __sincosf(ltv * PI_OVER_NB, &s1, &c1);
                    float sM = 0.f, cM = 1.f;
                    float add = __half2float(wc[12]);
#pragma unroll
                    for (int m = 1; m < 12; m++) {
                        float ns = sM * c1 + cM * s1;
                        float nc = cM * c1 - sM * s1;
                        sM = ns; cM = nc;
                        add += ns * __half2float(wc[m]) + nc * __half2float(wc[12 + m]);
                    }
                    *(__half*)(smem + LTT + (uint32_t)(ip * 4 + la) * TSB + (uint32_t)cch * 2u) =
                        __float2half(ltv + add);
                }
            }
        } else {
            // ===== decoder epilogue (heads 0..7) =====
#pragma unroll 1
            for (int h = 0; h < 8; h++) {
                const char* dqp = smem + AST + (uint32_t)(ip * 4 + la) * TSB + (uint32_t)h * 64u;
                const char* ltp = smem + LTT + (uint32_t)(ip * 4 + lb) * TSB + (uint32_t)h * 64u;
                float sc = 0.f;
#pragma unroll
                for (int i = 0; i < 4; i++) {
                    uint4 ua = *(const uint4*)(dqp + i * 16);
                    uint4 ub = *(const uint4*)(ltp + i * 16);
                    const __half2* pa = (const __half2*)&ua;
                    const __half2* pb = (const __half2*)&ub;
#pragma unroll
                    for (int j2 = 0; j2 < 4; j2++) {
                        float2 fa = __half22float2(pa[j2]);
                        float2 fb = __half22float2(pb[j2]);
                        sc += fa.x * fb.x + fa.y * fb.y;
                    }
                }
                float mx = sc;
                mx = fmaxf(mx, __shfl_xor_sync(FULL, mx, 1, 4));
                mx = fmaxf(mx, __shfl_xor_sync(FULL, mx, 2, 4));
                float ex = __expf(sc - mx);
                float ssum = ex;
                ssum += __shfl_xor_sync(FULL, ssum, 1, 4);
                ssum += __shfl_xor_sync(FULL, ssum, 2, 4);
                float av = ex / ssum;
                float a4[4];
#pragma unroll
                for (int t2 = 0; t2 < 4; t2++) a4[t2] = __shfl_sync(FULL, av, la * 4 + t2, 16);

                // v stage: thread (ip, pos=la, cg=lb) -> ch = h*32 + lb*8 .. +7 (coalesced)
                float o[8];
#pragma unroll
                for (int i = 0; i < 8; i++) o[i] = 0.f;
#pragma unroll
                for (int t2 = 0; t2 < 4; t2++) {
                    uint4 lv = *(const uint4*)(smem + LTT + (uint32_t)(ip * 4 + t2) * TSB +
                                               (uint32_t)h * 64u + (uint32_t)lb * 16u);
                    const __half2* hp = (const __half2*)&lv;
                    float a = a4[t2];
#pragma unroll
                    for (int j2 = 0; j2 < 4; j2++) {
                        float2 f = __half22float2(hp[j2]);
                        o[2 * j2]     += a * f.x;
                        o[2 * j2 + 1] += a * f.y;
                    }
                }
                int j = ip * 4 + la;
                uint32_t xoff = (uint32_t)j * 512u + ((uint32_t)((h * 4 + lb) ^ (j & 7)) << 4);
                uint4 xv = *(const uint4*)(smem + XTHI + xoff);
                const __half2* xp = (const __half2*)&xv;
                float4 o0, o1;
                {
                    float2 f0 = __half22float2(xp[0]);
                    float2 f1 = __half22float2(xp[1]);
                    float2 f2 = __half22float2(xp[2]);
                    float2 f3 = __half22float2(xp[3]);
                    o0.x = o[0] + f0.x; o0.y = o[1] + f0.y;
                    o0.z = o[2] + f1.x; o0.w = o[3] + f1.y;
                    o1.x = o[4] + f2.x; o1.y = o[5] + f2.y;
                    o1.z = o[6] + f3.x; o1.w = o[7] + f3.y;
                }
                float* ob = og + (size_t)la * 262144 + (size_t)(hp0 + ip) * 256 + h * 32 + lb * 8;
                *(float4*)ob = o0;
                *(float4*)(ob + 4) = o1;
            }
        }
        __syncthreads();                         // stg_t (AST) free for next round staging

        if (r < 2) stage8(sb, r + 1, 0, 0, tid);
    }
}

extern "C" void kernel_launch(void* const* d_in, const int* in_sizes, int n_in,
                              void* d_out, int out_size)
{
    const float* x       = (const float*)d_in[0];
    const float* weights = (const float*)d_in[1];
    const float* latent  = (const float*)d_in[2];
    const float* enc_w   = (const float*)d_in[3];
    const float* enc_b   = (const float*)d_in[4];
    const float* dec_w   = (const float*)d_in[5];
    const float* dec_b   = (const float*)d_in[6];
    float* out = (float*)d_out;

    prep_kernel<<<(768 * 32 + 255) / 256, 256>>>(enc_w, dec_w);

    cudaFuncSetAttribute(NeuralSpectralBlock1d_4509715661385_kernel,
                         cudaFuncAttributeMaxDynamicSharedMemorySize, (int)SMEM_REQ);
    NeuralSpectralBlock1d_4509715661385_kernel<<<2048, THREADS, SMEM_REQ>>>(
        x, weights, latent, enc_b, dec_b, out);
}